// round 5
// baseline (speedup 1.0000x reference)
#include <cuda_runtime.h>

// Problem shape (fixed): B=1, N=4096, H=16, D=64, C=1024
#define N_SEQ 4096
#define C_DIM 1024
#define H_HEADS 16
#define D_HEAD 64
// softmax scale folded with log2(e): exp(x*0.125) = exp2(x*0.125*1.442695)
#define QSCALE 0.18033688f

// Scratch (allocation-free rule)
__device__ float g_q[H_HEADS * N_SEQ * D_HEAD];   // [H][N][D]
__device__ float g_k[H_HEADS * N_SEQ * D_HEAD];
__device__ float g_v[H_HEADS * N_SEQ * D_HEAD];
__device__ float g_ao[N_SEQ * C_DIM];             // [N][C]

// ---- tf32 helpers ---------------------------------------------------------
__device__ __forceinline__ unsigned f2tf(float f) {
    unsigned u;
    asm("cvt.rna.tf32.f32 %0, %1;" : "=r"(u) : "f"(f));
    return u;
}
__device__ __forceinline__ void mma_tf32(float* c, unsigned a0, unsigned a1,
                                         unsigned a2, unsigned a3,
                                         unsigned b0, unsigned b1) {
    asm volatile(
        "mma.sync.aligned.m16n8k8.row.col.f32.tf32.tf32.f32 "
        "{%0,%1,%2,%3}, {%4,%5,%6,%7}, {%8,%9}, {%0,%1,%2,%3};"
        : "+f"(c[0]), "+f"(c[1]), "+f"(c[2]), "+f"(c[3])
        : "r"(a0), "r"(a1), "r"(a2), "r"(a3), "r"(b0), "r"(b1));
}

// ---------------------------------------------------------------------------
// tf32 GEMM: out[m,o] = sum_c A[m,c] * W[o,c]. Block tile 128x128x16,
// 128 threads = 4 warps, warp tile 64x64 (mt x nt = 4 x 8).
// Register prefetch of next k-tile hides LDG latency behind MMAs.
// EPI=0: A = x (arg), scatter into g_q/g_k/g_v. EPI=1: A = g_ao, +bias -> out.
// Smem stride 136 (== 8 mod 32): frag loads bank 8*tg+g bijective -> CF.
// ---------------------------------------------------------------------------
#define GS 136
template <int EPI>
__global__ __launch_bounds__(128, 2)
void gemm_tf32_kernel(const float* __restrict__ A_in, const float* __restrict__ W,
                      const float* __restrict__ bias, float* __restrict__ out) {
    const float* __restrict__ A = (EPI == 0) ? A_in : (const float*)g_ao;

    __shared__ unsigned As[16][GS];   // [k][m]
    __shared__ unsigned Bs[16][GS];   // [k][o]
    const int t = threadIdx.x;         // 0..127
    const int warp = t >> 5;
    const int lane = t & 31;
    const int g = lane >> 2;           // 0..7
    const int tg = lane & 3;           // 0..3
    const int wm = (warp & 1) * 64;    // 2 warps along M
    const int wn = (warp >> 1) * 64;   // 2 warps along N
    const int m0 = blockIdx.y * 128;
    const int o0 = blockIdx.x * 128;

    float acc[4][8][4];
#pragma unroll
    for (int i = 0; i < 4; ++i)
#pragma unroll
        for (int j = 0; j < 8; ++j)
#pragma unroll
            for (int c = 0; c < 4; ++c) acc[i][j][c] = 0.f;

    // Prefetch registers: thread t owns A row m0+t and W row o0+t (16 cols each)
    float4 pa[4], pb[4];
    const float* Arow = A + (m0 + t) * C_DIM;
    const float* Wrow = W + (o0 + t) * C_DIM;
#pragma unroll
    for (int i = 0; i < 4; ++i) {
        pa[i] = *(const float4*)&Arow[i * 4];
        pb[i] = *(const float4*)&Wrow[i * 4];
    }

    for (int k0 = 0; k0 < C_DIM; k0 += 16) {
        __syncthreads();
        // store prefetched tile (per STS: fixed k row, t spans 32 consecutive -> CF)
        const float* af4 = (const float*)pa;
        const float* bf4 = (const float*)pb;
#pragma unroll
        for (int i = 0; i < 16; ++i) {
            As[i][t] = f2tf(af4[i]);
            Bs[i][t] = f2tf(bf4[i]);
        }
        __syncthreads();
        // issue next tile's loads; latency hidden by the MMAs below
        if (k0 + 16 < C_DIM) {
#pragma unroll
            for (int i = 0; i < 4; ++i) {
                pa[i] = *(const float4*)&Arow[k0 + 16 + i * 4];
                pb[i] = *(const float4*)&Wrow[k0 + 16 + i * 4];
            }
        }
#pragma unroll
        for (int ks = 0; ks < 16; ks += 8) {
            unsigned af[4][4];
#pragma unroll
            for (int mt = 0; mt < 4; ++mt) {
                const int rb = wm + mt * 16;
                af[mt][0] = As[ks + tg][rb + g];
                af[mt][1] = As[ks + tg][rb + g + 8];
                af[mt][2] = As[ks + tg + 4][rb + g];
                af[mt][3] = As[ks + tg + 4][rb + g + 8];
            }
#pragma unroll
            for (int nt = 0; nt < 8; ++nt) {
                const unsigned bf0 = Bs[ks + tg][wn + nt * 8 + g];
                const unsigned bf1 = Bs[ks + tg + 4][wn + nt * 8 + g];
#pragma unroll
                for (int mt = 0; mt < 4; ++mt)
                    mma_tf32(acc[mt][nt], af[mt][0], af[mt][1], af[mt][2],
                             af[mt][3], bf0, bf1);
            }
        }
    }

#pragma unroll
    for (int mt = 0; mt < 4; ++mt) {
        const int r0 = m0 + wm + mt * 16 + g;
#pragma unroll
        for (int nt = 0; nt < 8; ++nt) {
            const int o = o0 + wn + nt * 8 + 2 * tg;
            if (EPI == 0) {
                const int which = o >> 10;
                const int rem = o & 1023;
                const int h = rem >> 6;
                const int d = rem & 63;
                float* dst = (which == 0) ? g_q : (which == 1) ? g_k : g_v;
                *(float2*)&dst[(h * N_SEQ + r0) * D_HEAD + d] =
                    make_float2(acc[mt][nt][0], acc[mt][nt][1]);
                *(float2*)&dst[(h * N_SEQ + r0 + 8) * D_HEAD + d] =
                    make_float2(acc[mt][nt][2], acc[mt][nt][3]);
            } else {
                const float bx = bias[o], by = bias[o + 1];
                *(float2*)&out[r0 * C_DIM + o] =
                    make_float2(acc[mt][nt][0] + bx, acc[mt][nt][1] + by);
                *(float2*)&out[(r0 + 8) * C_DIM + o] =
                    make_float2(acc[mt][nt][2] + bx, acc[mt][nt][3] + by);
            }
        }
    }
}

// ---------------------------------------------------------------------------
// Flash attention, tf32. 256 threads = 8 warps, BQ=128 (16 q-rows/warp),
// KT=32. Q fragments register-resident for the whole kernel (scale folded
// in, exp2-domain softmax). K/V staged in smem; P via smem (warp-private).
// ---------------------------------------------------------------------------
#define BQ 128
#define KT 32
__global__ __launch_bounds__(256, 2)
void attn_kernel() {
    __shared__ unsigned Ks[KT][68];    // [key][d]  bank 4g+tg bijective
    __shared__ unsigned Vs[KT][72];    // [key][d]  bank 8tg+g bijective
    __shared__ unsigned Ps[BQ][36];    // [q][k]    ap loads 4g+tg bijective

    const int h = blockIdx.y;
    const int q0 = (gridDim.x - 1 - blockIdx.x) * BQ;  // heavy tiles first
    const int tid = threadIdx.x;
    const int warp = tid >> 5;
    const int lane = tid & 31;
    const int g = lane >> 2;
    const int tg = lane & 3;
    const int wq = warp * 16;

    const float* Qg = g_q + h * N_SEQ * D_HEAD;
    const float* Kg = g_k + h * N_SEQ * D_HEAD;
    const float* Vg = g_v + h * N_SEQ * D_HEAD;

    // ---- Q fragments direct to registers (reused across all KV tiles)
    unsigned qf[8][4];
    {
        const float* Qr0 = Qg + (q0 + wq + g) * D_HEAD;
        const float* Qr1 = Qr0 + 8 * D_HEAD;
#pragma unroll
        for (int ks = 0; ks < 8; ++ks) {
            const int kc = ks * 8;
            qf[ks][0] = f2tf(Qr0[kc + tg] * QSCALE);
            qf[ks][1] = f2tf(Qr1[kc + tg] * QSCALE);
            qf[ks][2] = f2tf(Qr0[kc + tg + 4] * QSCALE);
            qf[ks][3] = f2tf(Qr1[kc + tg + 4] * QSCALE);
        }
    }

    float o_acc[8][4];
#pragma unroll
    for (int dt = 0; dt < 8; ++dt)
#pragma unroll
        for (int c = 0; c < 4; ++c) o_acc[dt][c] = 0.f;
    float m0_ = -1e30f, m1_ = -1e30f, l0_ = 0.f, l1_ = 0.f;

    const int nkt = (q0 + BQ) / KT;
    for (int jt = 0; jt < nkt; ++jt) {
        const int k0 = jt * KT;
        __syncthreads();
        for (int i = tid; i < KT * 16; i += 256) {
            const int r = i >> 4, c = (i & 15) * 4;
            float4 kv = *(const float4*)&Kg[(k0 + r) * D_HEAD + c];
            Ks[r][c] = f2tf(kv.x); Ks[r][c + 1] = f2tf(kv.y);
            Ks[r][c + 2] = f2tf(kv.z); Ks[r][c + 3] = f2tf(kv.w);
            float4 vv = *(const float4*)&Vg[(k0 + r) * D_HEAD + c];
            Vs[r][c] = f2tf(vv.x); Vs[r][c + 1] = f2tf(vv.y);
            Vs[r][c + 2] = f2tf(vv.z); Vs[r][c + 3] = f2tf(vv.w);
        }
        __syncthreads();

        // ---- S = Q K^T  (warp: 16 rows x 32 keys, in registers)
        float s[4][4];
#pragma unroll
        for (int nt = 0; nt < 4; ++nt)
#pragma unroll
            for (int c = 0; c < 4; ++c) s[nt][c] = 0.f;
#pragma unroll
        for (int ks = 0; ks < 8; ++ks) {
            const int kc = ks * 8;
#pragma unroll
            for (int nt = 0; nt < 4; ++nt) {
                const unsigned bk0 = Ks[nt * 8 + g][kc + tg];
                const unsigned bk1 = Ks[nt * 8 + g][kc + tg + 4];
                mma_tf32(s[nt], qf[ks][0], qf[ks][1], qf[ks][2], qf[ks][3],
                         bk0, bk1);
            }
        }

        // ---- mask + online softmax in exp2 domain (scale pre-folded)
        const int r0 = q0 + wq + g;
        const int r1 = r0 + 8;
        const bool diag = (k0 + KT > q0 + wq);
        float mx0 = -1e30f, mx1 = -1e30f;
#pragma unroll
        for (int nt = 0; nt < 4; ++nt) {
            if (diag) {
                const int c0 = k0 + nt * 8 + 2 * tg;
                const int c1 = c0 + 1;
                if (c0 > r0) s[nt][0] = -1e30f;
                if (c1 > r0) s[nt][1] = -1e30f;
                if (c0 > r1) s[nt][2] = -1e30f;
                if (c1 > r1) s[nt][3] = -1e30f;
            }
            mx0 = fmaxf(mx0, fmaxf(s[nt][0], s[nt][1]));
            mx1 = fmaxf(mx1, fmaxf(s[nt][2], s[nt][3]));
        }
        mx0 = fmaxf(mx0, __shfl_xor_sync(0xffffffffu, mx0, 1));
        mx0 = fmaxf(mx0, __shfl_xor_sync(0xffffffffu, mx0, 2));
        mx1 = fmaxf(mx1, __shfl_xor_sync(0xffffffffu, mx1, 1));
        mx1 = fmaxf(mx1, __shfl_xor_sync(0xffffffffu, mx1, 2));

        const float nm0 = fmaxf(m0_, mx0);
        const float nm1 = fmaxf(m1_, mx1);
        const float corr0 = exp2f(m0_ - nm0);
        const float corr1 = exp2f(m1_ - nm1);
        m0_ = nm0; m1_ = nm1;

        float rs0 = 0.f, rs1 = 0.f;
#pragma unroll
        for (int nt = 0; nt < 4; ++nt) {
            const float p00 = exp2f(s[nt][0] - nm0);
            const float p01 = exp2f(s[nt][1] - nm0);
            const float p10 = exp2f(s[nt][2] - nm1);
            const float p11 = exp2f(s[nt][3] - nm1);
            rs0 += p00 + p01;
            rs1 += p10 + p11;
            const int cc = nt * 8 + 2 * tg;
            Ps[wq + g][cc] = f2tf(p00); Ps[wq + g][cc + 1] = f2tf(p01);
            Ps[wq + g + 8][cc] = f2tf(p10); Ps[wq + g + 8][cc + 1] = f2tf(p11);
        }
        rs0 += __shfl_xor_sync(0xffffffffu, rs0, 1);
        rs0 += __shfl_xor_sync(0xffffffffu, rs0, 2);
        rs1 += __shfl_xor_sync(0xffffffffu, rs1, 1);
        rs1 += __shfl_xor_sync(0xffffffffu, rs1, 2);
        l0_ = l0_ * corr0 + rs0;
        l1_ = l1_ * corr1 + rs1;

#pragma unroll
        for (int dt = 0; dt < 8; ++dt) {
            o_acc[dt][0] *= corr0; o_acc[dt][1] *= corr0;
            o_acc[dt][2] *= corr1; o_acc[dt][3] *= corr1;
        }
        __syncwarp();   // Ps rows wq..wq+15: written & read by this warp only

        // ---- O += P V
#pragma unroll
        for (int ks = 0; ks < 4; ++ks) {
            const int kc = ks * 8;
            const unsigned ap0 = Ps[wq + g][kc + tg];
            const unsigned ap1 = Ps[wq + g + 8][kc + tg];
            const unsigned ap2 = Ps[wq + g][kc + tg + 4];
            const unsigned ap3 = Ps[wq + g + 8][kc + tg + 4];
#pragma unroll
            for (int dt = 0; dt < 8; ++dt) {
                const unsigned bv0 = Vs[kc + tg][dt * 8 + g];
                const unsigned bv1 = Vs[kc + tg + 4][dt * 8 + g];
                mma_tf32(o_acc[dt], ap0, ap1, ap2, ap3, bv0, bv1);
            }
        }
    }

    // ---- normalize + write [N][C]
    const float inv0 = 1.f / l0_;
    const float inv1 = 1.f / l1_;
    const int n0 = q0 + wq + g;
#pragma unroll
    for (int dt = 0; dt < 8; ++dt) {
        const int col = h * D_HEAD + dt * 8 + 2 * tg;
        *(float2*)&g_ao[n0 * C_DIM + col] =
            make_float2(o_acc[dt][0] * inv0, o_acc[dt][1] * inv0);
        *(float2*)&g_ao[(n0 + 8) * C_DIM + col] =
            make_float2(o_acc[dt][2] * inv1, o_acc[dt][3] * inv1);
    }
}

// ---------------------------------------------------------------------------
extern "C" void kernel_launch(void* const* d_in, const int* in_sizes, int n_in,
                              void* d_out, int out_size) {
    const float* x      = (const float*)d_in[0];
    const float* w_qkv  = (const float*)d_in[1];
    const float* w_proj = (const float*)d_in[2];
    const float* b_proj = (const float*)d_in[3];
    float* out = (float*)d_out;

    gemm_tf32_kernel<0><<<dim3(3 * C_DIM / 128, N_SEQ / 128), 128>>>(
        x, w_qkv, nullptr, nullptr);
    attn_kernel<<<dim3(N_SEQ / BQ, H_HEADS), 256>>>();
    gemm_tf32_kernel<1><<<dim3(C_DIM / 128, N_SEQ / 128), 128>>>(
        nullptr, w_proj, b_proj, out);
}

// round 10
// speedup vs baseline: 1.5379x; 1.5379x over previous
#include <cuda_runtime.h>
#include <cuda_fp16.h>

// Problem shape (fixed): B=1, N=4096, H=16, D=64, C=1024
#define N_SEQ 4096
#define C_DIM 1024
#define H_HEADS 16
#define D_HEAD 64
// softmax scale folded with log2(e): exp(x*0.125) = exp2(x*0.18033688)
#define QSCALE 0.18033688f

// Scratch (allocation-free rule)
__device__ float g_q[H_HEADS * N_SEQ * D_HEAD];   // [H][N][D]
__device__ float g_k[H_HEADS * N_SEQ * D_HEAD];
__device__ float g_v[H_HEADS * N_SEQ * D_HEAD];
__device__ float g_ao[N_SEQ * C_DIM];             // [N][C]

// ---- fp16 helpers ---------------------------------------------------------
__device__ __forceinline__ unsigned pack_h2(float a, float b) {
    __half2 h = __floats2half2_rn(a, b);
    return *(unsigned*)&h;
}
// m16n8k16 row.col f16 inputs, f32 accum
__device__ __forceinline__ void mma_f16(float* c, unsigned a0, unsigned a1,
                                        unsigned a2, unsigned a3,
                                        unsigned b0, unsigned b1) {
    asm volatile(
        "mma.sync.aligned.m16n8k16.row.col.f32.f16.f16.f32 "
        "{%0,%1,%2,%3}, {%4,%5,%6,%7}, {%8,%9}, {%0,%1,%2,%3};"
        : "+f"(c[0]), "+f"(c[1]), "+f"(c[2]), "+f"(c[3])
        : "r"(a0), "r"(a1), "r"(a2), "r"(a3), "r"(b0), "r"(b1));
}

// ---------------------------------------------------------------------------
// fp16 GEMM: out[m,o] = sum_c A[m,c] * W[o,c]. Block 128x128, k-tile 16,
// double-buffered smem, 256 thr = 8 warps, warp tile 64x32.
// Smem [m][k-pair] stride 12 (half2): frag bank = 12g+tg mod 32 bijective.
// EPI=0: scatter qkv. EPI=1: A = g_ao (device symbol), +bias -> out.
// ---------------------------------------------------------------------------
template <int EPI>
__global__ __launch_bounds__(256, 2)
void gemm_f16_kernel(const float* __restrict__ A_in, const float* __restrict__ W,
                     const float* __restrict__ bias, float* __restrict__ out) {
    const float* __restrict__ A = (EPI == 0) ? A_in : (const float*)g_ao;

    __shared__ __half2 As[2][128][12];   // [stage][m][k-pair 0..7]
    __shared__ __half2 Bs[2][128][12];   // [stage][o][k-pair]
    const int t = threadIdx.x;
    const int warp = t >> 5;
    const int lane = t & 31;
    const int g = lane >> 2;
    const int tg = lane & 3;
    const int wm = (warp & 1) * 64;
    const int wn = (warp >> 1) * 32;
    const int m0 = blockIdx.y * 128;
    const int o0 = blockIdx.x * 128;
    const int lr = t >> 1;             // 0..127 row
    const int lh = (t & 1) * 8;        // k offset 0/8

    float acc[4][4][4];
#pragma unroll
    for (int i = 0; i < 4; ++i)
#pragma unroll
        for (int j = 0; j < 4; ++j)
#pragma unroll
            for (int c = 0; c < 4; ++c) acc[i][j][c] = 0.f;

    const float* Arow = A + (m0 + lr) * C_DIM + lh;
    const float* Wrow = W + (o0 + lr) * C_DIM + lh;

    // prologue: tile 0 -> stage 0
    {
        float4 a0 = *(const float4*)Arow;
        float4 a1 = *(const float4*)(Arow + 4);
        float4 b0 = *(const float4*)Wrow;
        float4 b1 = *(const float4*)(Wrow + 4);
        __half2* pA = &As[0][lr][(t & 1) * 4];
        pA[0] = __floats2half2_rn(a0.x, a0.y);
        pA[1] = __floats2half2_rn(a0.z, a0.w);
        pA[2] = __floats2half2_rn(a1.x, a1.y);
        pA[3] = __floats2half2_rn(a1.z, a1.w);
        __half2* pB = &Bs[0][lr][(t & 1) * 4];
        pB[0] = __floats2half2_rn(b0.x, b0.y);
        pB[1] = __floats2half2_rn(b0.z, b0.w);
        pB[2] = __floats2half2_rn(b1.x, b1.y);
        pB[3] = __floats2half2_rn(b1.z, b1.w);
    }
    __syncthreads();

    for (int kt = 0; kt < C_DIM / 16; ++kt) {
        const int cur = kt & 1;
        const bool more = (kt + 1) < C_DIM / 16;
        float4 na0, na1, nb0, nb1;
        if (more) {
            const float* An = Arow + (kt + 1) * 16;
            const float* Wn = Wrow + (kt + 1) * 16;
            na0 = *(const float4*)An;
            na1 = *(const float4*)(An + 4);
            nb0 = *(const float4*)Wn;
            nb1 = *(const float4*)(Wn + 4);
        }
        // compute current stage: one k16 chunk, 4mt x 4nt MMAs
        unsigned af[4][4];
#pragma unroll
        for (int mt = 0; mt < 4; ++mt) {
            const int rb = wm + mt * 16;
            af[mt][0] = *(const unsigned*)&As[cur][rb + g][tg];
            af[mt][1] = *(const unsigned*)&As[cur][rb + g + 8][tg];
            af[mt][2] = *(const unsigned*)&As[cur][rb + g][tg + 4];
            af[mt][3] = *(const unsigned*)&As[cur][rb + g + 8][tg + 4];
        }
#pragma unroll
        for (int nt = 0; nt < 4; ++nt) {
            const unsigned bf0 = *(const unsigned*)&Bs[cur][wn + nt * 8 + g][tg];
            const unsigned bf1 = *(const unsigned*)&Bs[cur][wn + nt * 8 + g][tg + 4];
#pragma unroll
            for (int mt = 0; mt < 4; ++mt)
                mma_f16(acc[mt][nt], af[mt][0], af[mt][1], af[mt][2], af[mt][3],
                        bf0, bf1);
        }
        if (more) {
            const int nxt = cur ^ 1;
            __half2* pA = &As[nxt][lr][(t & 1) * 4];
            pA[0] = __floats2half2_rn(na0.x, na0.y);
            pA[1] = __floats2half2_rn(na0.z, na0.w);
            pA[2] = __floats2half2_rn(na1.x, na1.y);
            pA[3] = __floats2half2_rn(na1.z, na1.w);
            __half2* pB = &Bs[nxt][lr][(t & 1) * 4];
            pB[0] = __floats2half2_rn(nb0.x, nb0.y);
            pB[1] = __floats2half2_rn(nb0.z, nb0.w);
            pB[2] = __floats2half2_rn(nb1.x, nb1.y);
            pB[3] = __floats2half2_rn(nb1.z, nb1.w);
        }
        __syncthreads();
    }

    // epilogue: thread owns rows g/g+8, cols 2tg/2tg+1 per 16x8 tile
#pragma unroll
    for (int mt = 0; mt < 4; ++mt) {
        const int r0 = m0 + wm + mt * 16 + g;
#pragma unroll
        for (int nt = 0; nt < 4; ++nt) {
            const int o = o0 + wn + nt * 8 + 2 * tg;
            if (EPI == 0) {
                const int which = o >> 10;
                const int rem = o & 1023;
                const int h = rem >> 6;
                const int d = rem & 63;
                float* dst = (which == 0) ? g_q : (which == 1) ? g_k : g_v;
                *(float2*)&dst[(h * N_SEQ + r0) * D_HEAD + d] =
                    make_float2(acc[mt][nt][0], acc[mt][nt][1]);
                *(float2*)&dst[(h * N_SEQ + r0 + 8) * D_HEAD + d] =
                    make_float2(acc[mt][nt][2], acc[mt][nt][3]);
            } else {
                const float bx = bias[o], by = bias[o + 1];
                *(float2*)&out[r0 * C_DIM + o] =
                    make_float2(acc[mt][nt][0] + bx, acc[mt][nt][1] + by);
                *(float2*)&out[(r0 + 8) * C_DIM + o] =
                    make_float2(acc[mt][nt][2] + bx, acc[mt][nt][3] + by);
            }
        }
    }
}

// ---------------------------------------------------------------------------
// Flash attention, fp16 tensor cores. 256 thr = 8 warps, BQ=128 (16 q/warp),
// KT=32. Q frags + P held in registers (FA2 layout identity: S C-frag ==
// PV A-frag for m16n8k16). V stored key-transposed so PV B-frags are single
// 4B conflict-free loads. No P smem tile at all.
// ---------------------------------------------------------------------------
#define BQ 128
#define KT 32
__global__ __launch_bounds__(256)
void attn_kernel() {
    __shared__ __half2 Ks[KT][36];   // [key][d-pair]  bank 4g+tg bijective
    __shared__ __half Vsh[D_HEAD][40]; // [d][key] transposed; pair loads CF

    const int h = blockIdx.y;
    const int q0 = (gridDim.x - 1 - blockIdx.x) * BQ;  // heavy tiles first
    const int tid = threadIdx.x;
    const int warp = tid >> 5;
    const int lane = tid & 31;
    const int g = lane >> 2;
    const int tg = lane & 3;
    const int wq = warp * 16;

    const float* Qg = g_q + h * N_SEQ * D_HEAD;
    const float* Kg = g_k + h * N_SEQ * D_HEAD;
    const float* Vg = g_v + h * N_SEQ * D_HEAD;

    // ---- Q fragments (scaled) register-resident for whole kernel
    unsigned qf[4][4];   // [k16-chunk][a0..a3]
    {
        const float* Qr0 = Qg + (q0 + wq + g) * D_HEAD;
        const float* Qr1 = Qr0 + 8 * D_HEAD;
#pragma unroll
        for (int kc = 0; kc < 4; ++kc) {
            const int d0 = kc * 16 + 2 * tg;
            float2 x0 = *(const float2*)&Qr0[d0];
            float2 x1 = *(const float2*)&Qr1[d0];
            float2 x2 = *(const float2*)&Qr0[d0 + 8];
            float2 x3 = *(const float2*)&Qr1[d0 + 8];
            qf[kc][0] = pack_h2(x0.x * QSCALE, x0.y * QSCALE);
            qf[kc][1] = pack_h2(x1.x * QSCALE, x1.y * QSCALE);
            qf[kc][2] = pack_h2(x2.x * QSCALE, x2.y * QSCALE);
            qf[kc][3] = pack_h2(x3.x * QSCALE, x3.y * QSCALE);
        }
    }

    float o_acc[8][4];
#pragma unroll
    for (int dt = 0; dt < 8; ++dt)
#pragma unroll
        for (int c = 0; c < 4; ++c) o_acc[dt][c] = 0.f;
    float m0_ = -1e30f, m1_ = -1e30f, l0_ = 0.f, l1_ = 0.f;

    const int nkt = (q0 + BQ) / KT;
    for (int jt = 0; jt < nkt; ++jt) {
        const int k0 = jt * KT;
        __syncthreads();
        for (int i = tid; i < KT * 16; i += 256) {
            const int r = i >> 4;
            const int c4 = (i & 15) * 4;
            float4 kv = *(const float4*)&Kg[(k0 + r) * D_HEAD + c4];
            Ks[r][c4 / 2]     = __floats2half2_rn(kv.x, kv.y);
            Ks[r][c4 / 2 + 1] = __floats2half2_rn(kv.z, kv.w);
            float4 vv = *(const float4*)&Vg[(k0 + r) * D_HEAD + c4];
            Vsh[c4 + 0][r] = __float2half_rn(vv.x);   // transposed
            Vsh[c4 + 1][r] = __float2half_rn(vv.y);
            Vsh[c4 + 2][r] = __float2half_rn(vv.z);
            Vsh[c4 + 3][r] = __float2half_rn(vv.w);
        }
        __syncthreads();

        // ---- S = Q K^T (warp: 16 q-rows x 32 keys) in registers
        float s[4][4];
#pragma unroll
        for (int nt = 0; nt < 4; ++nt)
#pragma unroll
            for (int c = 0; c < 4; ++c) s[nt][c] = 0.f;
#pragma unroll
        for (int kc = 0; kc < 4; ++kc) {
#pragma unroll
            for (int nt = 0; nt < 4; ++nt) {
                const unsigned bk0 =
                    *(const unsigned*)&Ks[nt * 8 + g][kc * 8 + tg];
                const unsigned bk1 =
                    *(const unsigned*)&Ks[nt * 8 + g][kc * 8 + tg + 4];
                mma_f16(s[nt], qf[kc][0], qf[kc][1], qf[kc][2], qf[kc][3],
                        bk0, bk1);
            }
        }

        // ---- mask + online softmax (exp2 domain; scale pre-folded)
        const int r0 = q0 + wq + g;
        const int r1 = r0 + 8;
        const bool diag = (k0 + KT > q0 + wq);
        float mx0 = -1e30f, mx1 = -1e30f;
#pragma unroll
        for (int nt = 0; nt < 4; ++nt) {
            if (diag) {
                const int c0 = k0 + nt * 8 + 2 * tg;
                const int c1 = c0 + 1;
                if (c0 > r0) s[nt][0] = -1e30f;
                if (c1 > r0) s[nt][1] = -1e30f;
                if (c0 > r1) s[nt][2] = -1e30f;
                if (c1 > r1) s[nt][3] = -1e30f;
            }
            mx0 = fmaxf(mx0, fmaxf(s[nt][0], s[nt][1]));
            mx1 = fmaxf(mx1, fmaxf(s[nt][2], s[nt][3]));
        }
        mx0 = fmaxf(mx0, __shfl_xor_sync(0xffffffffu, mx0, 1));
        mx0 = fmaxf(mx0, __shfl_xor_sync(0xffffffffu, mx0, 2));
        mx1 = fmaxf(mx1, __shfl_xor_sync(0xffffffffu, mx1, 1));
        mx1 = fmaxf(mx1, __shfl_xor_sync(0xffffffffu, mx1, 2));

        const float nm0 = fmaxf(m0_, mx0);
        const float nm1 = fmaxf(m1_, mx1);
        const float corr0 = exp2f(m0_ - nm0);
        const float corr1 = exp2f(m1_ - nm1);
        m0_ = nm0; m1_ = nm1;

        float rs0 = 0.f, rs1 = 0.f;
#pragma unroll
        for (int nt = 0; nt < 4; ++nt) {
            s[nt][0] = exp2f(s[nt][0] - nm0);
            s[nt][1] = exp2f(s[nt][1] - nm0);
            s[nt][2] = exp2f(s[nt][2] - nm1);
            s[nt][3] = exp2f(s[nt][3] - nm1);
            rs0 += s[nt][0] + s[nt][1];
            rs1 += s[nt][2] + s[nt][3];
        }
        rs0 += __shfl_xor_sync(0xffffffffu, rs0, 1);
        rs0 += __shfl_xor_sync(0xffffffffu, rs0, 2);
        rs1 += __shfl_xor_sync(0xffffffffu, rs1, 1);
        rs1 += __shfl_xor_sync(0xffffffffu, rs1, 2);
        l0_ = l0_ * corr0 + rs0;
        l1_ = l1_ * corr1 + rs1;

        // P -> fp16 A-frags in registers (C-frag layout == A-frag layout)
        unsigned ap[2][4];
#pragma unroll
        for (int kc = 0; kc < 2; ++kc) {
            ap[kc][0] = pack_h2(s[2 * kc][0], s[2 * kc][1]);
            ap[kc][1] = pack_h2(s[2 * kc][2], s[2 * kc][3]);
            ap[kc][2] = pack_h2(s[2 * kc + 1][0], s[2 * kc + 1][1]);
            ap[kc][3] = pack_h2(s[2 * kc + 1][2], s[2 * kc + 1][3]);
        }

#pragma unroll
        for (int dt = 0; dt < 8; ++dt) {
            o_acc[dt][0] *= corr0; o_acc[dt][1] *= corr0;
            o_acc[dt][2] *= corr1; o_acc[dt][3] *= corr1;
        }

        // ---- O += P V  (B-frags from transposed V, key pairs packed)
#pragma unroll
        for (int kc = 0; kc < 2; ++kc) {
#pragma unroll
            for (int dt = 0; dt < 8; ++dt) {
                const unsigned bv0 =
                    *(const unsigned*)&Vsh[dt * 8 + g][kc * 16 + 2 * tg];
                const unsigned bv1 =
                    *(const unsigned*)&Vsh[dt * 8 + g][kc * 16 + 2 * tg + 8];
                mma_f16(o_acc[dt], ap[kc][0], ap[kc][1], ap[kc][2], ap[kc][3],
                        bv0, bv1);
            }
        }
    }

    // ---- normalize + write [N][C]
    const float inv0 = 1.f / l0_;
    const float inv1 = 1.f / l1_;
    const int n0 = q0 + wq + g;
#pragma unroll
    for (int dt = 0; dt < 8; ++dt) {
        const int col = h * D_HEAD + dt * 8 + 2 * tg;
        *(float2*)&g_ao[n0 * C_DIM + col] =
            make_float2(o_acc[dt][0] * inv0, o_acc[dt][1] * inv0);
        *(float2*)&g_ao[(n0 + 8) * C_DIM + col] =
            make_float2(o_acc[dt][2] * inv1, o_acc[dt][3] * inv1);
    }
}

// ---------------------------------------------------------------------------
extern "C" void kernel_launch(void* const* d_in, const int* in_sizes, int n_in,
                              void* d_out, int out_size) {
    const float* x      = (const float*)d_in[0];
    const float* w_qkv  = (const float*)d_in[1];
    const float* w_proj = (const float*)d_in[2];
    const float* b_proj = (const float*)d_in[3];
    float* out = (float*)d_out;

    gemm_f16_kernel<0><<<dim3(3 * C_DIM / 128, N_SEQ / 128), 256>>>(
        x, w_qkv, nullptr, nullptr);
    attn_kernel<<<dim3(N_SEQ / BQ, H_HEADS), 256>>>();
    gemm_f16_kernel<1><<<dim3(C_DIM / 128, N_SEQ / 128), 256>>>(
        nullptr, w_proj, b_proj, out);
}

// round 11
// speedup vs baseline: 1.5705x; 1.0212x over previous
#include <cuda_runtime.h>
#include <cuda_fp16.h>

// Problem shape (fixed): B=1, N=4096, H=16, D=64, C=1024
#define N_SEQ 4096
#define C_DIM 1024
#define H_HEADS 16
#define D_HEAD 64
// softmax scale folded with log2(e): exp(x*0.125) = exp2(x*0.18033688)
#define QSCALE 0.18033688f

// Scratch (allocation-free rule) — all fp16
__device__ __half g_xh[N_SEQ * C_DIM];
__device__ __half g_wqkvh[3 * C_DIM * C_DIM];
__device__ __half g_wprojh[C_DIM * C_DIM];
__device__ __half g_qh[H_HEADS * N_SEQ * D_HEAD];   // [H][N][D], pre-scaled
__device__ __half g_kh[H_HEADS * N_SEQ * D_HEAD];
__device__ __half g_vh[H_HEADS * N_SEQ * D_HEAD];
__device__ __half g_aoh[N_SEQ * C_DIM];             // [N][C]

// ---- fp16 helpers ---------------------------------------------------------
__device__ __forceinline__ unsigned pack_h2(float a, float b) {
    __half2 h = __floats2half2_rn(a, b);
    return *(unsigned*)&h;
}
__device__ __forceinline__ void mma_f16(float* c, unsigned a0, unsigned a1,
                                        unsigned a2, unsigned a3,
                                        unsigned b0, unsigned b1) {
    asm volatile(
        "mma.sync.aligned.m16n8k16.row.col.f32.f16.f16.f32 "
        "{%0,%1,%2,%3}, {%4,%5,%6,%7}, {%8,%9}, {%0,%1,%2,%3};"
        : "+f"(c[0]), "+f"(c[1]), "+f"(c[2]), "+f"(c[3])
        : "r"(a0), "r"(a1), "r"(a2), "r"(a3), "r"(b0), "r"(b1));
}

// ---------------------------------------------------------------------------
// Prep: convert fp32 inputs to fp16 once. 8 elems/thread, exact grid.
// ---------------------------------------------------------------------------
__global__ void prep_kernel(const float* __restrict__ x,
                            const float* __restrict__ wq,
                            const float* __restrict__ wp) {
    const int NX = N_SEQ * C_DIM / 8;          // 524288
    const int NWQ = 3 * C_DIM * C_DIM / 8;     // 393216
    const int NWP = C_DIM * C_DIM / 8;         // 131072
    int idx = blockIdx.x * blockDim.x + threadIdx.x;
    const float* src;
    __half* dst;
    int i;
    if (idx < NX) { src = x; dst = g_xh; i = idx; }
    else if (idx < NX + NWQ) { src = wq; dst = g_wqkvh; i = idx - NX; }
    else if (idx < NX + NWQ + NWP) { src = wp; dst = g_wprojh; i = idx - NX - NWQ; }
    else return;
    float4 a = ((const float4*)src)[2 * i];
    float4 b = ((const float4*)src)[2 * i + 1];
    __half2 h[4];
    h[0] = __floats2half2_rn(a.x, a.y);
    h[1] = __floats2half2_rn(a.z, a.w);
    h[2] = __floats2half2_rn(b.x, b.y);
    h[3] = __floats2half2_rn(b.z, b.w);
    ((uint4*)dst)[i] = *(uint4*)h;
}

// ---------------------------------------------------------------------------
// fp16 GEMM (fp16 in gmem): out[m,o] = sum_c A[m,c]*W[o,c]. Block 128x128,
// k-tile 16, double-buffered smem, 256 thr, warp tile 64x32.
// EPI=0: A=g_xh, W=g_wqkvh, scatter fp16 qkv (Q pre-scaled by QSCALE).
// EPI=1: A=g_aoh, W=g_wprojh, +bias -> fp32 out.
// ---------------------------------------------------------------------------
template <int EPI>
__global__ __launch_bounds__(256, 2)
void gemm_f16_kernel(const float* __restrict__ bias, float* __restrict__ out) {
    const __half* __restrict__ A = (EPI == 0) ? g_xh : g_aoh;
    const __half* __restrict__ W = (EPI == 0) ? g_wqkvh : g_wprojh;

    __shared__ __half2 As[2][128][12];   // [stage][m][k-pair]; frag bank 12g+tg CF
    __shared__ __half2 Bs[2][128][12];
    const int t = threadIdx.x;
    const int warp = t >> 5;
    const int lane = t & 31;
    const int g = lane >> 2;
    const int tg = lane & 3;
    const int wm = (warp & 1) * 64;
    const int wn = (warp >> 1) * 32;
    const int m0 = blockIdx.y * 128;
    const int o0 = blockIdx.x * 128;
    const int lr = t >> 1;             // row 0..127
    const int lsc = (t & 1) * 4;       // smem half2 col 0/4

    float acc[4][4][4];
#pragma unroll
    for (int i = 0; i < 4; ++i)
#pragma unroll
        for (int j = 0; j < 4; ++j)
#pragma unroll
            for (int c = 0; c < 4; ++c) acc[i][j][c] = 0.f;

    const __half* Arow = A + (m0 + lr) * C_DIM + (t & 1) * 8;
    const __half* Wrow = W + (o0 + lr) * C_DIM + (t & 1) * 8;

    // prologue: tile 0 -> stage 0 (one LDG.128 + one STS.128 per operand)
    *(uint4*)&As[0][lr][lsc] = *(const uint4*)Arow;
    *(uint4*)&Bs[0][lr][lsc] = *(const uint4*)Wrow;
    __syncthreads();

    for (int kt = 0; kt < C_DIM / 16; ++kt) {
        const int cur = kt & 1;
        const bool more = (kt + 1) < C_DIM / 16;
        uint4 na, nb;
        if (more) {
            na = *(const uint4*)(Arow + (kt + 1) * 16);
            nb = *(const uint4*)(Wrow + (kt + 1) * 16);
        }
        unsigned af[4][4];
#pragma unroll
        for (int mt = 0; mt < 4; ++mt) {
            const int rb = wm + mt * 16;
            af[mt][0] = *(const unsigned*)&As[cur][rb + g][tg];
            af[mt][1] = *(const unsigned*)&As[cur][rb + g + 8][tg];
            af[mt][2] = *(const unsigned*)&As[cur][rb + g][tg + 4];
            af[mt][3] = *(const unsigned*)&As[cur][rb + g + 8][tg + 4];
        }
#pragma unroll
        for (int nt = 0; nt < 4; ++nt) {
            const unsigned bf0 = *(const unsigned*)&Bs[cur][wn + nt * 8 + g][tg];
            const unsigned bf1 = *(const unsigned*)&Bs[cur][wn + nt * 8 + g][tg + 4];
#pragma unroll
            for (int mt = 0; mt < 4; ++mt)
                mma_f16(acc[mt][nt], af[mt][0], af[mt][1], af[mt][2], af[mt][3],
                        bf0, bf1);
        }
        if (more) {
            const int nxt = cur ^ 1;
            *(uint4*)&As[nxt][lr][lsc] = na;
            *(uint4*)&Bs[nxt][lr][lsc] = nb;
        }
        __syncthreads();
    }

#pragma unroll
    for (int mt = 0; mt < 4; ++mt) {
        const int r0 = m0 + wm + mt * 16 + g;
#pragma unroll
        for (int nt = 0; nt < 4; ++nt) {
            const int o = o0 + wn + nt * 8 + 2 * tg;
            if (EPI == 0) {
                const int which = o >> 10;
                const int rem = o & 1023;
                const int h = rem >> 6;
                const int d = rem & 63;
                __half* dst = (which == 0) ? g_qh : (which == 1) ? g_kh : g_vh;
                const float sc = (which == 0) ? QSCALE : 1.f;
                *(__half2*)&dst[(h * N_SEQ + r0) * D_HEAD + d] =
                    __floats2half2_rn(acc[mt][nt][0] * sc, acc[mt][nt][1] * sc);
                *(__half2*)&dst[(h * N_SEQ + r0 + 8) * D_HEAD + d] =
                    __floats2half2_rn(acc[mt][nt][2] * sc, acc[mt][nt][3] * sc);
            } else {
                const float bx = bias[o], by = bias[o + 1];
                *(float2*)&out[r0 * C_DIM + o] =
                    make_float2(acc[mt][nt][0] + bx, acc[mt][nt][1] + by);
                *(float2*)&out[(r0 + 8) * C_DIM + o] =
                    make_float2(acc[mt][nt][2] + bx, acc[mt][nt][3] + by);
            }
        }
    }
}

// ---------------------------------------------------------------------------
// Flash attention, fp16. 128 thr = 4 warps; BQ=128; warp tile = 32 q-rows
// (2 row-groups) so every K/V fragment LDS feeds 2 MMAs. Q frags + P in
// registers; V key-transposed in smem.
// ---------------------------------------------------------------------------
#define BQ 128
#define KT 32
__global__ __launch_bounds__(128)
void attn_kernel() {
    __shared__ __half2 Ks[KT][36];      // [key][d-pair]; frag bank 4g+tg CF
    __shared__ __half Vsh[D_HEAD][40];  // [d][key] transposed

    const int h = blockIdx.y;
    const int q0 = (gridDim.x - 1 - blockIdx.x) * BQ;  // heavy tiles first
    const int tid = threadIdx.x;
    const int warp = tid >> 5;
    const int lane = tid & 31;
    const int g = lane >> 2;
    const int tg = lane & 3;
    const int wq = warp * 32;

    const __half* Qh = g_qh + h * N_SEQ * D_HEAD;
    const __half* Kh = g_kh + h * N_SEQ * D_HEAD;
    const __half* Vh = g_vh + h * N_SEQ * D_HEAD;

    // ---- Q fragments: 2 row-groups x 4 k16-chunks, direct 4B loads
    unsigned qf[2][4][4];
#pragma unroll
    for (int rg = 0; rg < 2; ++rg) {
        const __half* Qr0 = Qh + (q0 + wq + rg * 16 + g) * D_HEAD;
        const __half* Qr1 = Qr0 + 8 * D_HEAD;
#pragma unroll
        for (int kc = 0; kc < 4; ++kc) {
            const int d0 = kc * 16 + 2 * tg;
            qf[rg][kc][0] = *(const unsigned*)&Qr0[d0];
            qf[rg][kc][1] = *(const unsigned*)&Qr1[d0];
            qf[rg][kc][2] = *(const unsigned*)&Qr0[d0 + 8];
            qf[rg][kc][3] = *(const unsigned*)&Qr1[d0 + 8];
        }
    }

    float o_acc[2][8][4];
#pragma unroll
    for (int rg = 0; rg < 2; ++rg)
#pragma unroll
        for (int dt = 0; dt < 8; ++dt)
#pragma unroll
            for (int c = 0; c < 4; ++c) o_acc[rg][dt][c] = 0.f;
    float m_[2][2], l_[2][2];
#pragma unroll
    for (int rg = 0; rg < 2; ++rg) {
        m_[rg][0] = -1e30f; m_[rg][1] = -1e30f;
        l_[rg][0] = 0.f; l_[rg][1] = 0.f;
    }

    const int nkt = (q0 + BQ) / KT;
    for (int jt = 0; jt < nkt; ++jt) {
        const int k0 = jt * KT;
        __syncthreads();
        // K: 32 rows x 8 uint4 (8 halves each)
        for (int i = tid; i < KT * 8; i += 128) {
            const int r = i >> 3;
            const int c = (i & 7) * 8;          // half index
            *(uint4*)&Ks[r][c >> 1] = *(const uint4*)&Kh[(k0 + r) * D_HEAD + c];
        }
        // V transposed: 32 rows x 16 uint2 (4 halves)
        for (int i = tid; i < KT * 16; i += 128) {
            const int r = i >> 4;
            const int c4 = (i & 15) * 4;
            uint2 vv = *(const uint2*)&Vh[(k0 + r) * D_HEAD + c4];
            const __half* hp = (const __half*)&vv;
            Vsh[c4 + 0][r] = hp[0];
            Vsh[c4 + 1][r] = hp[1];
            Vsh[c4 + 2][r] = hp[2];
            Vsh[c4 + 3][r] = hp[3];
        }
        __syncthreads();

        // ---- S = Q K^T: K frags shared across both row-groups
        float s[2][4][4];
#pragma unroll
        for (int rg = 0; rg < 2; ++rg)
#pragma unroll
            for (int nt = 0; nt < 4; ++nt)
#pragma unroll
                for (int c = 0; c < 4; ++c) s[rg][nt][c] = 0.f;
#pragma unroll
        for (int kc = 0; kc < 4; ++kc) {
#pragma unroll
            for (int nt = 0; nt < 4; ++nt) {
                const unsigned bk0 = *(const unsigned*)&Ks[nt * 8 + g][kc * 8 + tg];
                const unsigned bk1 = *(const unsigned*)&Ks[nt * 8 + g][kc * 8 + tg + 4];
                mma_f16(s[0][nt], qf[0][kc][0], qf[0][kc][1], qf[0][kc][2],
                        qf[0][kc][3], bk0, bk1);
                mma_f16(s[1][nt], qf[1][kc][0], qf[1][kc][1], qf[1][kc][2],
                        qf[1][kc][3], bk0, bk1);
            }
        }

        // ---- mask + online softmax per row-group (exp2 domain)
        unsigned ap[2][2][4];
#pragma unroll
        for (int rg = 0; rg < 2; ++rg) {
            const int r0 = q0 + wq + rg * 16 + g;
            const int r1 = r0 + 8;
            const bool diag = (k0 + KT > q0 + wq + rg * 16);
            float mx0 = -1e30f, mx1 = -1e30f;
#pragma unroll
            for (int nt = 0; nt < 4; ++nt) {
                if (diag) {
                    const int c0 = k0 + nt * 8 + 2 * tg;
                    const int c1 = c0 + 1;
                    if (c0 > r0) s[rg][nt][0] = -1e30f;
                    if (c1 > r0) s[rg][nt][1] = -1e30f;
                    if (c0 > r1) s[rg][nt][2] = -1e30f;
                    if (c1 > r1) s[rg][nt][3] = -1e30f;
                }
                mx0 = fmaxf(mx0, fmaxf(s[rg][nt][0], s[rg][nt][1]));
                mx1 = fmaxf(mx1, fmaxf(s[rg][nt][2], s[rg][nt][3]));
            }
            mx0 = fmaxf(mx0, __shfl_xor_sync(0xffffffffu, mx0, 1));
            mx0 = fmaxf(mx0, __shfl_xor_sync(0xffffffffu, mx0, 2));
            mx1 = fmaxf(mx1, __shfl_xor_sync(0xffffffffu, mx1, 1));
            mx1 = fmaxf(mx1, __shfl_xor_sync(0xffffffffu, mx1, 2));

            const float nm0 = fmaxf(m_[rg][0], mx0);
            const float nm1 = fmaxf(m_[rg][1], mx1);
            const float corr0 = exp2f(m_[rg][0] - nm0);
            const float corr1 = exp2f(m_[rg][1] - nm1);
            m_[rg][0] = nm0; m_[rg][1] = nm1;

            float rs0 = 0.f, rs1 = 0.f;
#pragma unroll
            for (int nt = 0; nt < 4; ++nt) {
                s[rg][nt][0] = exp2f(s[rg][nt][0] - nm0);
                s[rg][nt][1] = exp2f(s[rg][nt][1] - nm0);
                s[rg][nt][2] = exp2f(s[rg][nt][2] - nm1);
                s[rg][nt][3] = exp2f(s[rg][nt][3] - nm1);
                rs0 += s[rg][nt][0] + s[rg][nt][1];
                rs1 += s[rg][nt][2] + s[rg][nt][3];
            }
            rs0 += __shfl_xor_sync(0xffffffffu, rs0, 1);
            rs0 += __shfl_xor_sync(0xffffffffu, rs0, 2);
            rs1 += __shfl_xor_sync(0xffffffffu, rs1, 1);
            rs1 += __shfl_xor_sync(0xffffffffu, rs1, 2);
            l_[rg][0] = l_[rg][0] * corr0 + rs0;
            l_[rg][1] = l_[rg][1] * corr1 + rs1;

            // P -> A-frags (C-frag layout == A-frag layout)
#pragma unroll
            for (int kc = 0; kc < 2; ++kc) {
                ap[rg][kc][0] = pack_h2(s[rg][2 * kc][0], s[rg][2 * kc][1]);
                ap[rg][kc][1] = pack_h2(s[rg][2 * kc][2], s[rg][2 * kc][3]);
                ap[rg][kc][2] = pack_h2(s[rg][2 * kc + 1][0], s[rg][2 * kc + 1][1]);
                ap[rg][kc][3] = pack_h2(s[rg][2 * kc + 1][2], s[rg][2 * kc + 1][3]);
            }
#pragma unroll
            for (int dt = 0; dt < 8; ++dt) {
                o_acc[rg][dt][0] *= corr0; o_acc[rg][dt][1] *= corr0;
                o_acc[rg][dt][2] *= corr1; o_acc[rg][dt][3] *= corr1;
            }
        }

        // ---- O += P V: V frags shared across both row-groups
#pragma unroll
        for (int kc = 0; kc < 2; ++kc) {
#pragma unroll
            for (int dt = 0; dt < 8; ++dt) {
                const unsigned bv0 =
                    *(const unsigned*)&Vsh[dt * 8 + g][kc * 16 + 2 * tg];
                const unsigned bv1 =
                    *(const unsigned*)&Vsh[dt * 8 + g][kc * 16 + 2 * tg + 8];
                mma_f16(o_acc[0][dt], ap[0][kc][0], ap[0][kc][1], ap[0][kc][2],
                        ap[0][kc][3], bv0, bv1);
                mma_f16(o_acc[1][dt], ap[1][kc][0], ap[1][kc][1], ap[1][kc][2],
                        ap[1][kc][3], bv0, bv1);
            }
        }
    }

    // ---- normalize + write fp16 [N][C]
#pragma unroll
    for (int rg = 0; rg < 2; ++rg) {
        const float inv0 = 1.f / l_[rg][0];
        const float inv1 = 1.f / l_[rg][1];
        const int n0 = q0 + wq + rg * 16 + g;
#pragma unroll
        for (int dt = 0; dt < 8; ++dt) {
            const int col = h * D_HEAD + dt * 8 + 2 * tg;
            *(__half2*)&g_aoh[n0 * C_DIM + col] =
                __floats2half2_rn(o_acc[rg][dt][0] * inv0, o_acc[rg][dt][1] * inv0);
            *(__half2*)&g_aoh[(n0 + 8) * C_DIM + col] =
                __floats2half2_rn(o_acc[rg][dt][2] * inv1, o_acc[rg][dt][3] * inv1);
        }
    }
}

// ---------------------------------------------------------------------------
extern "C" void kernel_launch(void* const* d_in, const int* in_sizes, int n_in,
                              void* d_out, int out_size) {
    const float* x      = (const float*)d_in[0];
    const float* w_qkv  = (const float*)d_in[1];
    const float* w_proj = (const float*)d_in[2];
    const float* b_proj = (const float*)d_in[3];
    float* out = (float*)d_out;

    prep_kernel<<<4096, 256>>>(x, w_qkv, w_proj);
    gemm_f16_kernel<0><<<dim3(3 * C_DIM / 128, N_SEQ / 128), 256>>>(nullptr, nullptr);
    attn_kernel<<<dim3(N_SEQ / BQ, H_HEADS), 128>>>();
    gemm_f16_kernel<1><<<dim3(C_DIM / 128, N_SEQ / 128), 256>>>(b_proj, out);
}